// round 13
// baseline (speedup 1.0000x reference)
#include <cuda_runtime.h>
#include <cuda_fp16.h>
#include <cstdint>

#define NUM_NODES 65536
#define NGRAPH    1024
#define GSIZE     64
#define HID       256
#define NH1       128
#define EDGES     2097152

// ---------------- scratch ----------------
__device__ int    g_deg[NUM_NODES];
__device__ __align__(16) __half g_w1h[NH1 * 256];   // W1 rows 1..256, transposed [n][k]
__device__ __align__(16) __half g_w2h[NH1 * NH1];   // W2 transposed [n][k]

// ---------------- pre-kernel: zero deg + convert/transpose weights ----------------
__global__ void conv_kernel(const float* __restrict__ W1,
                            const float* __restrict__ W2) {
    int t = blockIdx.x * blockDim.x + threadIdx.x;        // 32768 threads
    reinterpret_cast<int2*>(g_deg)[t] = make_int2(0, 0);
    {   // W1t: n = t&127, k = t>>7 (0..255); source row 1+k
        int n = t & 127, k = t >> 7;
        g_w1h[n * 256 + k] = __float2half_rn(W1[(1 + k) * NH1 + n]);
    }
    if (t < NH1 * NH1) {
        int n = t & 127, k = t >> 7;
        g_w2h[n * NH1 + k] = __float2half_rn(W2[k * NH1 + n]);
    }
}

// ---------------- degree histogram ----------------
__global__ void deg_kernel(const int* __restrict__ src) {
    int i = blockIdx.x * blockDim.x + threadIdx.x;
    int4 v = reinterpret_cast<const int4*>(src)[i];
    atomicAdd(&g_deg[v.x], 1);
    atomicAdd(&g_deg[v.y], 1);
    atomicAdd(&g_deg[v.z], 1);
    atomicAdd(&g_deg[v.w], 1);
}

// ---------------- mma.sync m16n8k16 f16 (fp32 accum) ----------------
__device__ __forceinline__ void mma16(float d[4], const uint32_t a[4],
                                      uint32_t b0, uint32_t b1) {
    asm volatile(
        "mma.sync.aligned.m16n8k16.row.col.f32.f16.f16.f32 "
        "{%0,%1,%2,%3}, {%4,%5,%6,%7}, {%8,%9}, {%0,%1,%2,%3};"
        : "+f"(d[0]), "+f"(d[1]), "+f"(d[2]), "+f"(d[3])
        : "r"(a[0]), "r"(a[1]), "r"(a[2]), "r"(a[3]), "r"(b0), "r"(b1));
}
// pack (lo, hi) -> f16x2 (round-to-nearest)
__device__ __forceinline__ uint32_t cvt2(float lo, float hi) {
    uint32_t r;
    asm("cvt.rn.f16x2.f32 %0, %1, %2;" : "=r"(r) : "f"(hi), "f"(lo));
    return r;
}
__device__ __forceinline__ uint32_t smem_u32(const void* p) {
    uint32_t a;
    asm("{ .reg .u64 t; cvta.to.shared.u64 t, %1; cvt.u32.u64 %0, t; }"
        : "=r"(a) : "l"(p));
    return a;
}
#define CP16(dst, src) \
    asm volatile("cp.async.cg.shared.global [%0], [%1], 16;" \
                 :: "r"(dst), "l"(src) : "memory")
#define CPCOMMIT() asm volatile("cp.async.commit_group;" ::: "memory")
#define CPWAIT(n)  asm volatile("cp.async.wait_group %0;" :: "n"(n) : "memory")

__device__ __forceinline__ float silu(float x) { return x / (1.0f + __expf(-x)); }

// ---------------- smem layout (bytes) ----------------
// A ring : 3 x [128 rows][36 f32] = 3 x 18432 @ 0      (55296)
// B ring : 3 x [128 n][20 half2]  = 3 x 10240 @ 55296  (30720) end 86016
//          (GEMM2 W2 chunks reuse B bufs 0/1)
// H      : [128][68 half2] = 34816 @ 0   overlays A ring after GEMM1
// sC     : 512 f32 @ 86016  (b1 | b2 | W3 | W1row0)
// sConn  : 128 f32 @ 88064
// sLog   : 128 f32 @ 88576
// sRed   : 8192 B (2048 f32 = [128][16]) @ 89088   end 97280
// sDeg   : 512 B  @ A-ring buf2 (RA(2)) -- free until chunk 2 staged
#define RA(i)     ((i) * 18432)
#define RB(i)     (55296 + (i) * 10240)
#define OFF_C     86016
#define OFF_CONN  88064
#define OFF_LOG   88576
#define OFF_RED   89088
#define SMEM_BYTES 97280

#define APITCH  36   /* f32,  36%32==4  -> conflict-light LDS.64 frag loads */
#define BPITCH2 20   /* half2, 20*la+lb distinct mod 32 -> conflict-free   */
#define HPITCH2 68   /* half2, 4*la+lb  distinct mod 32 -> conflict-free   */

// 512 threads, 16 warps in 4x4 (M x N); warp tile 32x32
__global__ void __launch_bounds__(512, 2)
mlp_kernel(const float* __restrict__ X,  const float* __restrict__ W1,
           const float* __restrict__ b1, const float* __restrict__ b2,
           const float* __restrict__ W3, const float* __restrict__ b3,
           const float* __restrict__ kT, float* __restrict__ out) {
    extern __shared__ char smem[];
    const uint32_t sb = smem_u32(smem);
    float* sC    = reinterpret_cast<float*>(smem + OFF_C);
    float* sConn = reinterpret_cast<float*>(smem + OFF_CONN);
    float* sLog  = reinterpret_cast<float*>(smem + OFF_LOG);
    float* sRed  = reinterpret_cast<float*>(smem + OFF_RED);

    const int tid  = threadIdx.x;                 // 512 threads, 16 warps
    const int wid  = tid >> 5;
    const int lane = tid & 31;
    const int la   = lane >> 2;                   // 0..7
    const int lb   = lane & 3;                    // 0..3
    const int wm   = wid & 3;                     // M block (32 rows)
    const int wn   = wid >> 2;                    // N block (32 cols), 0..3
    const int row0 = blockIdx.x * 128;            // 2 graphs per CTA

    // ---- staging helpers ----
    auto stageA = [&](int c, int ring) {          // X fp32 -> A ring (1024 float4)
#pragma unroll
        for (int p = 0; p < 2; ++p) {
            int idx = tid + 512 * p;
            int m = idx >> 3, kq = idx & 7;
            uint32_t dst = sb + RA(ring) + (uint32_t)(m * APITCH + 4 * kq) * 4u;
            const float* src = X + (size_t)(row0 + m) * HID + c * 32 + 4 * kq;
            CP16(dst, src);
        }
    };
    auto stageB1 = [&](int c, int ring) {         // g_w1h -> B ring (512 x 16B)
        int n = tid >> 2, g = tid & 3;
        uint32_t dst = sb + RB(ring) + (uint32_t)(n * 80 + g * 16);
        const char* src = reinterpret_cast<const char*>(g_w1h) +
                          (size_t)n * 512 + c * 64 + g * 16;
        CP16(dst, src);
    };
    auto stageW2 = [&](int c, int bi) {           // g_w2h -> B buf bi
        int n = tid >> 2, g = tid & 3;
        uint32_t dst = sb + RB(bi) + (uint32_t)(n * 80 + g * 16);
        const char* src = reinterpret_cast<const char*>(g_w2h) +
                          (size_t)n * 256 + c * 64 + g * 16;
        CP16(dst, src);
        CPCOMMIT();
    };

    // ---- constants + degrees ----
    if (tid < 128) {
        sC[tid]       = b1[tid];
        sC[128 + tid] = b2[tid];
        sC[256 + tid] = W3[tid];
        sC[384 + tid] = W1[tid];                  // W1 row 0 (conn column)
    }
    float b3v = __ldg(b3);
    float ikT = 1.0f / __ldg(kT);
    int* sDeg = reinterpret_cast<int*>(smem + RA(2));
    if (tid < 128) sDeg[tid] = g_deg[row0 + tid];
    __syncthreads();                              // sDeg visible

    // kick pipeline: chunks 0,1 in flight while we compute ranks
    stageA(0, 0); stageB1(0, 0); CPCOMMIT();
    stageA(1, 1); stageB1(1, 1); CPCOMMIT();

    // ---- connectivity: stable per-graph degree rank (2 graphs) ----
    if (tid < 128) {
        int gg = tid >> 6, li = tid & 63, base = gg * 64;
        int di = sDeg[tid], rk = 0;
#pragma unroll 8
        for (int j = 0; j < GSIZE; ++j) {
            int dj = sDeg[base + j];
            rk += (dj < di) || (dj == di && j < li);
        }
        sConn[base + rk] = (float)li * (1.0f / 64.0f);
    }
    __syncthreads();                              // sConn visible

    // ---- GEMM1 acc init: b1[n] + conn[m] * W1row0[n]  (exact fp32) ----
    float acc[2][4][4];
    {
        float cn[2][2];
#pragma unroll
        for (int mt = 0; mt < 2; ++mt) {
            cn[mt][0] = sConn[wm * 32 + mt * 16 + la];
            cn[mt][1] = sConn[wm * 32 + mt * 16 + 8 + la];
        }
#pragma unroll
        for (int nt = 0; nt < 4; ++nt) {
            int n0 = wn * 32 + nt * 8 + 2 * lb;
            float w0 = sC[384 + n0], w1 = sC[384 + n0 + 1];
            float bb0 = sC[n0],      bb1 = sC[n0 + 1];
#pragma unroll
            for (int mt = 0; mt < 2; ++mt) {
                acc[mt][nt][0] = fmaf(cn[mt][0], w0, bb0);
                acc[mt][nt][1] = fmaf(cn[mt][0], w1, bb1);
                acc[mt][nt][2] = fmaf(cn[mt][1], w0, bb0);
                acc[mt][nt][3] = fmaf(cn[mt][1], w1, bb1);
            }
        }
    }

    // ---- GEMM1: [conn|X] @ W1, K=256 in 8 chunks of 32, 3-ring ----
#pragma unroll
    for (int c = 0; c < 8; ++c) {
        if (c < 7) { CPWAIT(1); } else { CPWAIT(0); }
        __syncthreads();                          // chunk c ready; MMA(c-1) done
        if (c < 6) { stageA(c + 2, (c + 2) % 3); stageB1(c + 2, (c + 2) % 3); CPCOMMIT(); }
        const float*    Af = reinterpret_cast<const float*>(smem + RA(c % 3));
        const uint32_t* Bt = reinterpret_cast<const uint32_t*>(smem + RB(c % 3));
#pragma unroll
        for (int kt = 0; kt < 2; ++kt) {          // 2 x k16
            int kb = kt * 16;
            uint32_t a[2][4];
#pragma unroll
            for (int mt = 0; mt < 2; ++mt) {
                int m0 = wm * 32 + mt * 16;
                float2 v0 = *reinterpret_cast<const float2*>(Af + (m0 + la) * APITCH + kb + 2 * lb);
                float2 v1 = *reinterpret_cast<const float2*>(Af + (m0 + 8 + la) * APITCH + kb + 2 * lb);
                float2 v2 = *reinterpret_cast<const float2*>(Af + (m0 + la) * APITCH + kb + 8 + 2 * lb);
                float2 v3 = *reinterpret_cast<const float2*>(Af + (m0 + 8 + la) * APITCH + kb + 8 + 2 * lb);
                a[mt][0] = cvt2(v0.x, v0.y);
                a[mt][1] = cvt2(v1.x, v1.y);
                a[mt][2] = cvt2(v2.x, v2.y);
                a[mt][3] = cvt2(v3.x, v3.y);
            }
#pragma unroll
            for (int nt = 0; nt < 4; ++nt) {
                int n0 = wn * 32 + nt * 8;
                uint32_t b0 = Bt[(n0 + la) * BPITCH2 + kt * 8 + lb];
                uint32_t b1 = Bt[(n0 + la) * BPITCH2 + kt * 8 + 4 + lb];
                mma16(acc[0][nt], a[0], b0, b1);
                mma16(acc[1][nt], a[1], b0, b1);
            }
        }
    }
    __syncthreads();                              // all MMA done before H/W2 writes

    // W2 chunks 0,1 in flight during epilogue1
    stageW2(0, 0);
    stageW2(1, 1);

    // ---- epilogue1: silu -> H (half2, overlays A ring) ----
    uint32_t* H2 = reinterpret_cast<uint32_t*>(smem);
#pragma unroll
    for (int mt = 0; mt < 2; ++mt) {
        int m0 = wm * 32 + mt * 16;
#pragma unroll
        for (int nt = 0; nt < 4; ++nt) {
            int nh = wn * 16 + nt * 4 + lb;       // half2 column index
            H2[(m0 + la) * HPITCH2 + nh]     = cvt2(silu(acc[mt][nt][0]), silu(acc[mt][nt][1]));
            H2[(m0 + 8 + la) * HPITCH2 + nh] = cvt2(silu(acc[mt][nt][2]), silu(acc[mt][nt][3]));
        }
    }

    // ---- GEMM2 acc init: b2[n] ----
#pragma unroll
    for (int nt = 0; nt < 4; ++nt) {
        int n0 = wn * 32 + nt * 8 + 2 * lb;
        float bb0 = sC[128 + n0], bb1 = sC[128 + n0 + 1];
#pragma unroll
        for (int mt = 0; mt < 2; ++mt) {
            acc[mt][nt][0] = bb0; acc[mt][nt][1] = bb1;
            acc[mt][nt][2] = bb0; acc[mt][nt][3] = bb1;
        }
    }

    // ---- GEMM2: H1 @ W2, K=128 in 4 chunks of 32, double-buffered ----
#pragma unroll
    for (int c = 0; c < 4; ++c) {
        if (c == 0) { CPWAIT(1); } else { CPWAIT(0); }
        __syncthreads();                          // W2 chunk ready; H visible; prev MMA done
        if (c == 1) stageW2(2, 0);
        if (c == 2) stageW2(3, 1);
        const uint32_t* Wt = reinterpret_cast<const uint32_t*>(smem + RB(c & 1));
#pragma unroll
        for (int kt = 0; kt < 2; ++kt) {
            int kh = c * 16 + kt * 8;             // half2 k-offset in H
            uint32_t a[2][4];
#pragma unroll
            for (int mt = 0; mt < 2; ++mt) {
                int m0 = wm * 32 + mt * 16;
                a[mt][0] = H2[(m0 + la) * HPITCH2 + kh + lb];
                a[mt][1] = H2[(m0 + 8 + la) * HPITCH2 + kh + lb];
                a[mt][2] = H2[(m0 + la) * HPITCH2 + kh + 4 + lb];
                a[mt][3] = H2[(m0 + 8 + la) * HPITCH2 + kh + 4 + lb];
            }
#pragma unroll
            for (int nt = 0; nt < 4; ++nt) {
                int n0 = wn * 32 + nt * 8;
                uint32_t b0 = Wt[(n0 + la) * BPITCH2 + kt * 8 + lb];
                uint32_t b1 = Wt[(n0 + la) * BPITCH2 + kt * 8 + 4 + lb];
                mma16(acc[0][nt], a[0], b0, b1);
                mma16(acc[1][nt], a[1], b0, b1);
            }
        }
    }
    __syncthreads();

    // ---- epilogue2: silu(D2) . W3 -> partials -> sRed [128][16] ----
#pragma unroll
    for (int mt = 0; mt < 2; ++mt) {
#pragma unroll
        for (int half = 0; half < 2; ++half) {
            float p = 0.0f;
#pragma unroll
            for (int nt = 0; nt < 4; ++nt) {
                int n0 = wn * 32 + nt * 8 + 2 * lb;
                float v0 = acc[mt][nt][half * 2 + 0];
                float v1 = acc[mt][nt][half * 2 + 1];
                p = fmaf(silu(v0), sC[256 + n0], p);
                p = fmaf(silu(v1), sC[256 + n0 + 1], p);
            }
            int m = wm * 32 + mt * 16 + half * 8 + la;
            sRed[m * 16 + wn * 4 + lb] = p;
        }
    }
    __syncthreads();

    if (tid < 128) {
        float s = 0.0f;
#pragma unroll
        for (int t = 0; t < 16; ++t) s += sRed[tid * 16 + t];
        sLog[tid] = (s + b3v) * ikT;
    }
    __syncthreads();

    // ---- per-graph softmax ----
    if (tid < 64) {
        int w = tid >> 5, l = tid & 31, base = w * 64;
        float a  = sLog[base + l];
        float b  = sLog[base + l + 32];
        float mx = fmaxf(a, b);
#pragma unroll
        for (int o = 16; o; o >>= 1) mx = fmaxf(mx, __shfl_xor_sync(0xffffffffu, mx, o));
        float e0 = expf(a - mx), e1 = expf(b - mx);
        float s = e0 + e1;
#pragma unroll
        for (int o = 16; o; o >>= 1) s += __shfl_xor_sync(0xffffffffu, s, o);
        float inv = 1.0f / s;
        out[row0 + base + l]      = e0 * inv;
        out[row0 + base + l + 32] = e1 * inv;
    }
}

// ---------------- launcher ----------------
extern "C" void kernel_launch(void* const* d_in, const int* in_sizes, int n_in,
                              void* d_out, int out_size) {
    const float* X  = (const float*)d_in[0];
    const float* W1 = (const float*)d_in[1];
    const float* b1 = (const float*)d_in[2];
    const float* W2 = (const float*)d_in[3];
    const float* b2 = (const float*)d_in[4];
    const float* W3 = (const float*)d_in[5];
    const float* b3 = (const float*)d_in[6];
    const float* kT = (const float*)d_in[7];
    const int*   ei = (const int*)d_in[8];
    float* out = (float*)d_out;

    conv_kernel<<<128, 256>>>(W1, W2);            // zero deg + fp16 weights
    deg_kernel<<<EDGES / 4 / 256, 256>>>(ei);

    cudaFuncSetAttribute(mlp_kernel, cudaFuncAttributeMaxDynamicSharedMemorySize,
                         SMEM_BYTES);
    mlp_kernel<<<NGRAPH / 2, 512, SMEM_BYTES>>>(X, W1, b1, b2, W3, b3, kT, out);
}

// round 15
// speedup vs baseline: 1.0847x; 1.0847x over previous
#include <cuda_runtime.h>
#include <cuda_fp16.h>
#include <cstdint>

#define NUM_NODES 65536
#define NGRAPH    1024
#define GSIZE     64
#define HID       256
#define NH1       128
#define EDGES     2097152

// ---------------- scratch ----------------
__device__ int    g_deg[NUM_NODES];
__device__ __align__(16) __half g_w1h[NH1 * 256];   // W1 rows 1..256, transposed [n][k]
__device__ __align__(16) __half g_w2h[NH1 * NH1];   // W2 transposed [n][k]

// ---------------- pre-kernel: zero deg + convert/transpose weights ----------------
__global__ void conv_kernel(const float* __restrict__ W1,
                            const float* __restrict__ W2) {
    int t = blockIdx.x * blockDim.x + threadIdx.x;        // 32768 threads
    reinterpret_cast<int2*>(g_deg)[t] = make_int2(0, 0);
    {   // W1t: n = t&127, k = t>>7 (0..255); source row 1+k
        int n = t & 127, k = t >> 7;
        g_w1h[n * 256 + k] = __float2half_rn(W1[(1 + k) * NH1 + n]);
    }
    if (t < NH1 * NH1) {
        int n = t & 127, k = t >> 7;
        g_w2h[n * NH1 + k] = __float2half_rn(W2[k * NH1 + n]);
    }
}

// ---------------- degree histogram ----------------
__global__ void deg_kernel(const int* __restrict__ src) {
    int i = blockIdx.x * blockDim.x + threadIdx.x;
    int4 v = reinterpret_cast<const int4*>(src)[i];
    atomicAdd(&g_deg[v.x], 1);
    atomicAdd(&g_deg[v.y], 1);
    atomicAdd(&g_deg[v.z], 1);
    atomicAdd(&g_deg[v.w], 1);
}

// ---------------- mma.sync m16n8k16 f16 (fp32 accum) ----------------
__device__ __forceinline__ void mma16(float d[4], const uint32_t a[4],
                                      uint32_t b0, uint32_t b1) {
    asm volatile(
        "mma.sync.aligned.m16n8k16.row.col.f32.f16.f16.f32 "
        "{%0,%1,%2,%3}, {%4,%5,%6,%7}, {%8,%9}, {%0,%1,%2,%3};"
        : "+f"(d[0]), "+f"(d[1]), "+f"(d[2]), "+f"(d[3])
        : "r"(a[0]), "r"(a[1]), "r"(a[2]), "r"(a[3]), "r"(b0), "r"(b1));
}
// pack (lo, hi) -> f16x2 (round-to-nearest)
__device__ __forceinline__ uint32_t cvt2(float lo, float hi) {
    uint32_t r;
    asm("cvt.rn.f16x2.f32 %0, %1, %2;" : "=r"(r) : "f"(hi), "f"(lo));
    return r;
}
__device__ __forceinline__ uint32_t smem_u32(const void* p) {
    uint32_t a;
    asm("{ .reg .u64 t; cvta.to.shared.u64 t, %1; cvt.u32.u64 %0, t; }"
        : "=r"(a) : "l"(p));
    return a;
}
#define CP16(dst, src) \
    asm volatile("cp.async.cg.shared.global [%0], [%1], 16;" \
                 :: "r"(dst), "l"(src) : "memory")
#define CPCOMMIT() asm volatile("cp.async.commit_group;" ::: "memory")
#define CPWAIT(n)  asm volatile("cp.async.wait_group %0;" :: "n"(n) : "memory")

__device__ __forceinline__ float silu(float x) { return x / (1.0f + __expf(-x)); }

// ---------------- smem layout (bytes), M=64 per CTA ----------------
// A ring : 3 x [64 rows][36 f32] = 3 x 9216 @ 0      (27648)
// B ring : 3 x [128 n][20 half2] = 3 x 10240 @ 27648 (30720) end 58368
//          (GEMM2 W2 chunks reuse B bufs 0/1)
// H      : [64][68 half2] = 17408 @ 0   overlays A ring after GEMM1
// sC     : 512 f32 @ 58368  (b1 | b2 | W3 | W1row0)
// sConn  : 64 f32  @ 60416
// sLog   : 64 f32  @ 60672
// sRed   : 4096 B ([64][16] f32) @ 60928   end 65024
// sDeg   : 256 B  @ A-ring buf2 (RA(2)) -- free until chunk 2 staged
#define RA(i)     ((i) * 9216)
#define RB(i)     (27648 + (i) * 10240)
#define OFF_C     58368
#define OFF_CONN  60416
#define OFF_LOG   60672
#define OFF_RED   60928
#define SMEM_BYTES 65024

#define APITCH  36   /* f32,  36%32==4  -> conflict-light LDS.64 frag loads */
#define BPITCH2 20   /* half2, 20*la+lb distinct mod 32 -> conflict-free   */
#define HPITCH2 68   /* half2, 4*la+lb  distinct mod 32 -> conflict-free   */

// 256 threads, 8 warps in 2x4 (M x N); warp tile 32x32; CTA tile 64x128
__global__ void __launch_bounds__(256, 3)
mlp_kernel(const float* __restrict__ X,  const float* __restrict__ W1,
           const float* __restrict__ b1, const float* __restrict__ b2,
           const float* __restrict__ W3, const float* __restrict__ b3,
           const float* __restrict__ kT, float* __restrict__ out) {
    extern __shared__ char smem[];
    const uint32_t sb = smem_u32(smem);
    float* sC    = reinterpret_cast<float*>(smem + OFF_C);
    float* sConn = reinterpret_cast<float*>(smem + OFF_CONN);
    float* sLog  = reinterpret_cast<float*>(smem + OFF_LOG);
    float* sRed  = reinterpret_cast<float*>(smem + OFF_RED);

    const int tid  = threadIdx.x;                 // 256 threads, 8 warps
    const int wid  = tid >> 5;
    const int lane = tid & 31;
    const int la   = lane >> 2;                   // 0..7
    const int lb   = lane & 3;                    // 0..3
    const int wm   = wid & 1;                     // M block (32 rows), 0..1
    const int wn   = wid >> 1;                    // N block (32 cols), 0..3
    const int row0 = blockIdx.x * GSIZE;          // 1 graph per CTA

    // ---- staging helpers ----
    auto stageA = [&](int c, int ring) {          // X fp32 -> A ring (512 float4)
#pragma unroll
        for (int p = 0; p < 2; ++p) {
            int idx = tid + 256 * p;              // 0..511
            int m = idx >> 3, kq = idx & 7;
            uint32_t dst = sb + RA(ring) + (uint32_t)(m * APITCH + 4 * kq) * 4u;
            const float* src = X + (size_t)(row0 + m) * HID + c * 32 + 4 * kq;
            CP16(dst, src);
        }
    };
    auto stageB1 = [&](int c, int ring) {         // g_w1h -> B ring (512 x 16B)
#pragma unroll
        for (int p = 0; p < 2; ++p) {
            int idx = tid + 256 * p;
            int n = idx >> 2, g = idx & 3;
            uint32_t dst = sb + RB(ring) + (uint32_t)(n * 80 + g * 16);
            const char* src = reinterpret_cast<const char*>(g_w1h) +
                              (size_t)n * 512 + c * 64 + g * 16;
            CP16(dst, src);
        }
    };
    auto stageW2 = [&](int c, int bi) {           // g_w2h -> B buf bi
#pragma unroll
        for (int p = 0; p < 2; ++p) {
            int idx = tid + 256 * p;
            int n = idx >> 2, g = idx & 3;
            uint32_t dst = sb + RB(bi) + (uint32_t)(n * 80 + g * 16);
            const char* src = reinterpret_cast<const char*>(g_w2h) +
                              (size_t)n * 256 + c * 64 + g * 16;
            CP16(dst, src);
        }
        CPCOMMIT();
    };

    // ---- constants + degrees ----
    if (tid < 128) {
        sC[tid]       = b1[tid];
        sC[128 + tid] = b2[tid];
        sC[256 + tid] = W3[tid];
        sC[384 + tid] = W1[tid];                  // W1 row 0 (conn column)
    }
    float b3v = __ldg(b3);
    float ikT = 1.0f / __ldg(kT);
    int* sDeg = reinterpret_cast<int*>(smem + RA(2));
    if (tid < GSIZE) sDeg[tid] = g_deg[row0 + tid];
    __syncthreads();                              // sDeg visible

    // kick pipeline: chunks 0,1 in flight while we compute ranks
    stageA(0, 0); stageB1(0, 0); CPCOMMIT();
    stageA(1, 1); stageB1(1, 1); CPCOMMIT();

    // ---- connectivity: stable degree rank (1 graph) ----
    if (tid < GSIZE) {
        int di = sDeg[tid], rk = 0;
#pragma unroll 8
        for (int j = 0; j < GSIZE; ++j) {
            int dj = sDeg[j];
            rk += (dj < di) || (dj == di && j < tid);
        }
        sConn[rk] = (float)tid * (1.0f / 64.0f);
    }
    __syncthreads();                              // sConn visible

    // ---- GEMM1 acc init: b1[n] + conn[m] * W1row0[n]  (exact fp32) ----
    float acc[2][4][4];
    {
        float cn[2][2];
#pragma unroll
        for (int mt = 0; mt < 2; ++mt) {
            cn[mt][0] = sConn[wm * 32 + mt * 16 + la];
            cn[mt][1] = sConn[wm * 32 + mt * 16 + 8 + la];
        }
#pragma unroll
        for (int nt = 0; nt < 4; ++nt) {
            int n0 = wn * 32 + nt * 8 + 2 * lb;
            float w0 = sC[384 + n0], w1 = sC[384 + n0 + 1];
            float bb0 = sC[n0],      bb1 = sC[n0 + 1];
#pragma unroll
            for (int mt = 0; mt < 2; ++mt) {
                acc[mt][nt][0] = fmaf(cn[mt][0], w0, bb0);
                acc[mt][nt][1] = fmaf(cn[mt][0], w1, bb1);
                acc[mt][nt][2] = fmaf(cn[mt][1], w0, bb0);
                acc[mt][nt][3] = fmaf(cn[mt][1], w1, bb1);
            }
        }
    }

    // ---- GEMM1: [conn|X] @ W1, K=256 in 8 chunks of 32, 3-ring ----
#pragma unroll
    for (int c = 0; c < 8; ++c) {
        if (c < 7) { CPWAIT(1); } else { CPWAIT(0); }
        __syncthreads();                          // chunk c ready; MMA(c-1) done
        if (c < 6) { stageA(c + 2, (c + 2) % 3); stageB1(c + 2, (c + 2) % 3); CPCOMMIT(); }
        const float*    Af = reinterpret_cast<const float*>(smem + RA(c % 3));
        const uint32_t* Bt = reinterpret_cast<const uint32_t*>(smem + RB(c % 3));
#pragma unroll
        for (int kt = 0; kt < 2; ++kt) {          // 2 x k16
            int kb = kt * 16;
            uint32_t a[2][4];
#pragma unroll
            for (int mt = 0; mt < 2; ++mt) {
                int m0 = wm * 32 + mt * 16;
                float2 v0 = *reinterpret_cast<const float2*>(Af + (m0 + la) * APITCH + kb + 2 * lb);
                float2 v1 = *reinterpret_cast<const float2*>(Af + (m0 + 8 + la) * APITCH + kb + 2 * lb);
                float2 v2 = *reinterpret_cast<const float2*>(Af + (m0 + la) * APITCH + kb + 8 + 2 * lb);
                float2 v3 = *reinterpret_cast<const float2*>(Af + (m0 + 8 + la) * APITCH + kb + 8 + 2 * lb);
                a[mt][0] = cvt2(v0.x, v0.y);
                a[mt][1] = cvt2(v1.x, v1.y);
                a[mt][2] = cvt2(v2.x, v2.y);
                a[mt][3] = cvt2(v3.x, v3.y);
            }
#pragma unroll
            for (int nt = 0; nt < 4; ++nt) {
                int n0 = wn * 32 + nt * 8;
                uint32_t b0 = Bt[(n0 + la) * BPITCH2 + kt * 8 + lb];
                uint32_t b1 = Bt[(n0 + la) * BPITCH2 + kt * 8 + 4 + lb];
                mma16(acc[0][nt], a[0], b0, b1);
                mma16(acc[1][nt], a[1], b0, b1);
            }
        }
    }
    __syncthreads();                              // all MMA done before H/W2 writes

    // W2 chunks 0,1 in flight during epilogue1
    stageW2(0, 0);
    stageW2(1, 1);

    // ---- epilogue1: silu -> H (half2, overlays A ring) ----
    uint32_t* H2 = reinterpret_cast<uint32_t*>(smem);
#pragma unroll
    for (int mt = 0; mt < 2; ++mt) {
        int m0 = wm * 32 + mt * 16;
#pragma unroll
        for (int nt = 0; nt < 4; ++nt) {
            int nh = wn * 16 + nt * 4 + lb;       // half2 column index, 0..63
            H2[(m0 + la) * HPITCH2 + nh]     = cvt2(silu(acc[mt][nt][0]), silu(acc[mt][nt][1]));
            H2[(m0 + 8 + la) * HPITCH2 + nh] = cvt2(silu(acc[mt][nt][2]), silu(acc[mt][nt][3]));
        }
    }

    // ---- GEMM2 acc init: b2[n] ----
#pragma unroll
    for (int nt = 0; nt < 4; ++nt) {
        int n0 = wn * 32 + nt * 8 + 2 * lb;
        float bb0 = sC[128 + n0], bb1 = sC[128 + n0 + 1];
#pragma unroll
        for (int mt = 0; mt < 2; ++mt) {
            acc[mt][nt][0] = bb0; acc[mt][nt][1] = bb1;
            acc[mt][nt][2] = bb0; acc[mt][nt][3] = bb1;
        }
    }

    // ---- GEMM2: H1 @ W2, K=128 in 4 chunks of 32, double-buffered ----
#pragma unroll
    for (int c = 0; c < 4; ++c) {
        if (c == 0) { CPWAIT(1); } else { CPWAIT(0); }
        __syncthreads();                          // W2 chunk ready; H visible; prev MMA done
        if (c == 1) stageW2(2, 0);
        if (c == 2) stageW2(3, 1);
        const uint32_t* Wt = reinterpret_cast<const uint32_t*>(smem + RB(c & 1));
#pragma unroll
        for (int kt = 0; kt < 2; ++kt) {
            int kh = c * 16 + kt * 8;             // half2 k-offset in H
            uint32_t a[2][4];
#pragma unroll
            for (int mt = 0; mt < 2; ++mt) {
                int m0 = wm * 32 + mt * 16;
                a[mt][0] = H2[(m0 + la) * HPITCH2 + kh + lb];
                a[mt][1] = H2[(m0 + 8 + la) * HPITCH2 + kh + lb];
                a[mt][2] = H2[(m0 + la) * HPITCH2 + kh + 4 + lb];
                a[mt][3] = H2[(m0 + 8 + la) * HPITCH2 + kh + 4 + lb];
            }
#pragma unroll
            for (int nt = 0; nt < 4; ++nt) {
                int n0 = wn * 32 + nt * 8;
                uint32_t b0 = Wt[(n0 + la) * BPITCH2 + kt * 8 + lb];
                uint32_t b1 = Wt[(n0 + la) * BPITCH2 + kt * 8 + 4 + lb];
                mma16(acc[0][nt], a[0], b0, b1);
                mma16(acc[1][nt], a[1], b0, b1);
            }
        }
    }
    __syncthreads();

    // ---- epilogue2: silu(D2) . W3 -> partials -> sRed [64][16] ----
#pragma unroll
    for (int mt = 0; mt < 2; ++mt) {
#pragma unroll
        for (int half = 0; half < 2; ++half) {
            float p = 0.0f;
#pragma unroll
            for (int nt = 0; nt < 4; ++nt) {
                int n0 = wn * 32 + nt * 8 + 2 * lb;
                float v0 = acc[mt][nt][half * 2 + 0];
                float v1 = acc[mt][nt][half * 2 + 1];
                p = fmaf(silu(v0), sC[256 + n0], p);
                p = fmaf(silu(v1), sC[256 + n0 + 1], p);
            }
            int m = wm * 32 + mt * 16 + half * 8 + la;   // 0..63
            sRed[m * 16 + wn * 4 + lb] = p;
        }
    }
    __syncthreads();

    if (tid < GSIZE) {
        float s = 0.0f;
#pragma unroll
        for (int t = 0; t < 16; ++t) s += sRed[tid * 16 + t];
        sLog[tid] = (s + b3v) * ikT;
    }
    __syncthreads();

    // ---- per-graph softmax: warp 0, each lane owns 2 logits ----
    if (tid < 32) {
        float a  = sLog[tid];
        float b  = sLog[tid + 32];
        float mx = fmaxf(a, b);
#pragma unroll
        for (int o = 16; o; o >>= 1) mx = fmaxf(mx, __shfl_xor_sync(0xffffffffu, mx, o));
        float e0 = expf(a - mx), e1 = expf(b - mx);
        float s = e0 + e1;
#pragma unroll
        for (int o = 16; o; o >>= 1) s += __shfl_xor_sync(0xffffffffu, s, o);
        float inv = 1.0f / s;
        out[row0 + tid]      = e0 * inv;
        out[row0 + tid + 32] = e1 * inv;
    }
}

// ---------------- launcher ----------------
extern "C" void kernel_launch(void* const* d_in, const int* in_sizes, int n_in,
                              void* d_out, int out_size) {
    const float* X  = (const float*)d_in[0];
    const float* W1 = (const float*)d_in[1];
    const float* b1 = (const float*)d_in[2];
    const float* W2 = (const float*)d_in[3];
    const float* b2 = (const float*)d_in[4];
    const float* W3 = (const float*)d_in[5];
    const float* b3 = (const float*)d_in[6];
    const float* kT = (const float*)d_in[7];
    const int*   ei = (const int*)d_in[8];
    float* out = (float*)d_out;

    conv_kernel<<<128, 256>>>(W1, W2);            // zero deg + fp16 weights
    deg_kernel<<<EDGES / 4 / 256, 256>>>(ei);

    cudaFuncSetAttribute(mlp_kernel, cudaFuncAttributeMaxDynamicSharedMemorySize,
                         SMEM_BYTES);
    mlp_kernel<<<NGRAPH, 256, SMEM_BYTES>>>(X, W1, b1, b2, W3, b3, kT, out);
}

// round 16
// speedup vs baseline: 1.0907x; 1.0055x over previous
#include <cuda_runtime.h>
#include <cuda_fp16.h>
#include <cstdint>

#define NUM_NODES 65536
#define NGRAPH    1024
#define GSIZE     64
#define HID       256
#define NH1       128
#define EDGES     2097152

// ---------------- scratch ----------------
__device__ int    g_deg[NUM_NODES];
__device__ __align__(16) __half g_w1h[NH1 * 256];   // W1 rows 1..256, transposed [n][k]
__device__ __align__(16) __half g_w2h[NH1 * NH1];   // W2 transposed [n][k]

// ---------------- pre-kernel: zero deg + coalesced transpose-convert ----------------
// 64 CTAs x 256 threads. CTAs 0..31: W1 tiles (8 k-tiles x 4 n-tiles);
// CTAs 32..47: W2 tiles (4 x 4). All CTAs zero a 4KB slice of g_deg.
__global__ void conv_kernel(const float* __restrict__ W1,
                            const float* __restrict__ W2) {
    __shared__ float sm[32][33];
    const int blk = blockIdx.x;
    const int t   = threadIdx.x;
    // zero g_deg: 64 CTAs x 256 thr x int4 = 65536 ints
    reinterpret_cast<int4*>(g_deg)[blk * 256 + t] = make_int4(0, 0, 0, 0);

    const int r = t >> 5, c = t & 31;
    if (blk < 32) {           // W1: k0 = (blk>>2)*32, n0 = (blk&3)*32, src row 1+k
        int k0 = (blk >> 2) * 32, n0 = (blk & 3) * 32;
#pragma unroll
        for (int p = 0; p < 4; ++p)
            sm[r + 8 * p][c] = W1[(size_t)(1 + k0 + r + 8 * p) * NH1 + n0 + c];
        __syncthreads();
#pragma unroll
        for (int p = 0; p < 4; ++p) {
            int n = r + 8 * p;
            g_w1h[(size_t)(n0 + n) * 256 + k0 + c] = __float2half_rn(sm[c][n]);
        }
    } else if (blk < 48) {    // W2: k0 = ((blk-32)>>2)*32, n0 = ((blk-32)&3)*32
        int b2 = blk - 32;
        int k0 = (b2 >> 2) * 32, n0 = (b2 & 3) * 32;
#pragma unroll
        for (int p = 0; p < 4; ++p)
            sm[r + 8 * p][c] = W2[(size_t)(k0 + r + 8 * p) * NH1 + n0 + c];
        __syncthreads();
#pragma unroll
        for (int p = 0; p < 4; ++p) {
            int n = r + 8 * p;
            g_w2h[(size_t)(n0 + n) * NH1 + k0 + c] = __float2half_rn(sm[c][n]);
        }
    }
}

// ---------------- degree histogram ----------------
__global__ void deg_kernel(const int* __restrict__ src) {
    int i = blockIdx.x * blockDim.x + threadIdx.x;
    int4 v = reinterpret_cast<const int4*>(src)[i];
    atomicAdd(&g_deg[v.x], 1);
    atomicAdd(&g_deg[v.y], 1);
    atomicAdd(&g_deg[v.z], 1);
    atomicAdd(&g_deg[v.w], 1);
}

// ---------------- mma.sync m16n8k16 f16 (fp32 accum) ----------------
__device__ __forceinline__ void mma16(float d[4], const uint32_t a[4],
                                      uint32_t b0, uint32_t b1) {
    asm volatile(
        "mma.sync.aligned.m16n8k16.row.col.f32.f16.f16.f32 "
        "{%0,%1,%2,%3}, {%4,%5,%6,%7}, {%8,%9}, {%0,%1,%2,%3};"
        : "+f"(d[0]), "+f"(d[1]), "+f"(d[2]), "+f"(d[3])
        : "r"(a[0]), "r"(a[1]), "r"(a[2]), "r"(a[3]), "r"(b0), "r"(b1));
}
__device__ __forceinline__ uint32_t cvt2(float lo, float hi) {
    uint32_t r;
    asm("cvt.rn.f16x2.f32 %0, %1, %2;" : "=r"(r) : "f"(hi), "f"(lo));
    return r;
}
__device__ __forceinline__ uint32_t smem_u32(const void* p) {
    uint32_t a;
    asm("{ .reg .u64 t; cvta.to.shared.u64 t, %1; cvt.u32.u64 %0, t; }"
        : "=r"(a) : "l"(p));
    return a;
}
#define CP16(dst, src) \
    asm volatile("cp.async.cg.shared.global [%0], [%1], 16;" \
                 :: "r"(dst), "l"(src) : "memory")
#define CPCOMMIT() asm volatile("cp.async.commit_group;" ::: "memory")
#define CPWAIT(n)  asm volatile("cp.async.wait_group %0;" :: "n"(n) : "memory")

__device__ __forceinline__ float silu(float x) { return x / (1.0f + __expf(-x)); }

// ---------------- smem layout (bytes), M=64 per CTA ----------------
// A ring : 3 x [64 rows][36 f32] = 3 x 9216 @ 0      (27648)
// B ring : 3 x [128 n][20 half2] = 3 x 10240 @ 27648 (30720) end 58368
// After GEMM1:
//   H  : [64][68 half2] = 17408 @ 0 (overlays A ring)
//   W2 : 4 chunks x 10240 @ 17408..58368 (overlays A-ring tail + B ring)
// sC     : 512 f32 @ 58368  (b1 | b2 | W3 | W1row0)
// sConn  : 64 f32  @ 60416
// sLog   : 64 f32  @ 60672
// sRed   : 4096 B ([64][16] f32) @ 60928   end 65024
// sDeg   : 256 B  @ A-ring buf2 (RA(2)) -- free until chunk 2 staged
#define RA(i)     ((i) * 9216)
#define RB(i)     (27648 + (i) * 10240)
#define WB(i)     (17408 + (i) * 10240)
#define OFF_C     58368
#define OFF_CONN  60416
#define OFF_LOG   60672
#define OFF_RED   60928
#define SMEM_BYTES 65024

#define APITCH  36   /* f32,  36%32==4  -> conflict-light LDS.64 frag loads */
#define BPITCH2 20   /* half2, 20*la+lb distinct mod 32 -> conflict-free   */
#define HPITCH2 68   /* half2, 4*la+lb  distinct mod 32 -> conflict-free   */

// 256 threads, 8 warps in 2x4 (M x N); warp tile 32x32; CTA tile 64x128
__global__ void __launch_bounds__(256, 3)
mlp_kernel(const float* __restrict__ X,  const float* __restrict__ W1,
           const float* __restrict__ b1, const float* __restrict__ b2,
           const float* __restrict__ W3, const float* __restrict__ b3,
           const float* __restrict__ kT, float* __restrict__ out) {
    extern __shared__ char smem[];
    const uint32_t sb = smem_u32(smem);
    float* sC    = reinterpret_cast<float*>(smem + OFF_C);
    float* sConn = reinterpret_cast<float*>(smem + OFF_CONN);
    float* sLog  = reinterpret_cast<float*>(smem + OFF_LOG);
    float* sRed  = reinterpret_cast<float*>(smem + OFF_RED);

    const int tid  = threadIdx.x;                 // 256 threads, 8 warps
    const int wid  = tid >> 5;
    const int lane = tid & 31;
    const int la   = lane >> 2;                   // 0..7
    const int lb   = lane & 3;                    // 0..3
    const int wm   = wid & 1;                     // M block (32 rows), 0..1
    const int wn   = wid >> 1;                    // N block (32 cols), 0..3
    const int row0 = blockIdx.x * GSIZE;          // 1 graph per CTA

    // ---- staging helpers ----
    auto stageA = [&](int c, int ring) {          // X fp32 -> A ring (512 float4)
#pragma unroll
        for (int p = 0; p < 2; ++p) {
            int idx = tid + 256 * p;              // 0..511
            int m = idx >> 3, kq = idx & 7;
            uint32_t dst = sb + RA(ring) + (uint32_t)(m * APITCH + 4 * kq) * 4u;
            const float* src = X + (size_t)(row0 + m) * HID + c * 32 + 4 * kq;
            CP16(dst, src);
        }
    };
    auto stageB1 = [&](int c, int ring) {         // g_w1h -> B ring (512 x 16B)
#pragma unroll
        for (int p = 0; p < 2; ++p) {
            int idx = tid + 256 * p;
            int n = idx >> 2, g = idx & 3;
            uint32_t dst = sb + RB(ring) + (uint32_t)(n * 80 + g * 16);
            const char* src = reinterpret_cast<const char*>(g_w1h) +
                              (size_t)n * 512 + c * 64 + g * 16;
            CP16(dst, src);
        }
    };

    // ---- constants + degrees ----
    if (tid < 128) {
        sC[tid]       = b1[tid];
        sC[128 + tid] = b2[tid];
        sC[256 + tid] = W3[tid];
        sC[384 + tid] = W1[tid];                  // W1 row 0 (conn column)
    }
    float b3v = __ldg(b3);
    float ikT = 1.0f / __ldg(kT);
    int* sDeg = reinterpret_cast<int*>(smem + RA(2));
    if (tid < GSIZE) sDeg[tid] = g_deg[row0 + tid];
    __syncthreads();                              // sDeg visible

    // kick pipeline: chunks 0,1 in flight while we compute ranks
    stageA(0, 0); stageB1(0, 0); CPCOMMIT();
    stageA(1, 1); stageB1(1, 1); CPCOMMIT();

    // ---- connectivity: stable degree rank (1 graph) ----
    if (tid < GSIZE) {
        int di = sDeg[tid], rk = 0;
#pragma unroll 8
        for (int j = 0; j < GSIZE; ++j) {
            int dj = sDeg[j];
            rk += (dj < di) || (dj == di && j < tid);
        }
        sConn[rk] = (float)tid * (1.0f / 64.0f);
    }
    __syncthreads();                              // sConn visible

    // ---- GEMM1 acc init: b1[n] + conn[m] * W1row0[n]  (exact fp32) ----
    float acc[2][4][4];
    {
        float cn[2][2];
#pragma unroll
        for (int mt = 0; mt < 2; ++mt) {
            cn[mt][0] = sConn[wm * 32 + mt * 16 + la];
            cn[mt][1] = sConn[wm * 32 + mt * 16 + 8 + la];
        }
#pragma unroll
        for (int nt = 0; nt < 4; ++nt) {
            int n0 = wn * 32 + nt * 8 + 2 * lb;
            float w0 = sC[384 + n0], w1 = sC[384 + n0 + 1];
            float bb0 = sC[n0],      bb1 = sC[n0 + 1];
#pragma unroll
            for (int mt = 0; mt < 2; ++mt) {
                acc[mt][nt][0] = fmaf(cn[mt][0], w0, bb0);
                acc[mt][nt][1] = fmaf(cn[mt][0], w1, bb1);
                acc[mt][nt][2] = fmaf(cn[mt][1], w0, bb0);
                acc[mt][nt][3] = fmaf(cn[mt][1], w1, bb1);
            }
        }
    }

    // ---- GEMM1: [conn|X] @ W1, K=256 in 8 chunks of 32, 3-ring ----
#pragma unroll
    for (int c = 0; c < 8; ++c) {
        if (c < 7) { CPWAIT(1); } else { CPWAIT(0); }
        __syncthreads();                          // chunk c ready; MMA(c-1) done
        if (c < 6) { stageA(c + 2, (c + 2) % 3); stageB1(c + 2, (c + 2) % 3); CPCOMMIT(); }
        const float*    Af = reinterpret_cast<const float*>(smem + RA(c % 3));
        const uint32_t* Bt = reinterpret_cast<const uint32_t*>(smem + RB(c % 3));
#pragma unroll
        for (int kt = 0; kt < 2; ++kt) {          // 2 x k16
            int kb = kt * 16;
            uint32_t a[2][4];
#pragma unroll
            for (int mt = 0; mt < 2; ++mt) {
                int m0 = wm * 32 + mt * 16;
                float2 v0 = *reinterpret_cast<const float2*>(Af + (m0 + la) * APITCH + kb + 2 * lb);
                float2 v1 = *reinterpret_cast<const float2*>(Af + (m0 + 8 + la) * APITCH + kb + 2 * lb);
                float2 v2 = *reinterpret_cast<const float2*>(Af + (m0 + la) * APITCH + kb + 8 + 2 * lb);
                float2 v3 = *reinterpret_cast<const float2*>(Af + (m0 + 8 + la) * APITCH + kb + 8 + 2 * lb);
                a[mt][0] = cvt2(v0.x, v0.y);
                a[mt][1] = cvt2(v1.x, v1.y);
                a[mt][2] = cvt2(v2.x, v2.y);
                a[mt][3] = cvt2(v3.x, v3.y);
            }
#pragma unroll
            for (int nt = 0; nt < 4; ++nt) {
                int n0 = wn * 32 + nt * 8;
                uint32_t b0 = Bt[(n0 + la) * BPITCH2 + kt * 8 + lb];
                uint32_t b1 = Bt[(n0 + la) * BPITCH2 + kt * 8 + 4 + lb];
                mma16(acc[0][nt], a[0], b0, b1);
                mma16(acc[1][nt], a[1], b0, b1);
            }
        }
    }
    __syncthreads();                              // all GEMM1 MMA done: A/B rings free

    // ---- stage ALL of W2 (4 chunks, 32KB data) in one shot ----
    // overlaps with epilogue1 below; regions WB(0..3) = 17408..58368
#pragma unroll
    for (int p = 0; p < 8; ++p) {
        int idx = tid + 256 * p;                  // 0..2047 granules (16B)
        int c = idx >> 9, q = idx & 511;          // chunk, within-chunk
        int n = q >> 2, g = q & 3;
        uint32_t dst = sb + WB(c) + (uint32_t)(n * 80 + g * 16);
        const char* src = reinterpret_cast<const char*>(g_w2h) +
                          (size_t)n * 256 + c * 64 + g * 16;
        CP16(dst, src);
    }
    CPCOMMIT();

    // ---- epilogue1: silu -> H (half2, bytes 0..17408) ----
    uint32_t* H2 = reinterpret_cast<uint32_t*>(smem);
#pragma unroll
    for (int mt = 0; mt < 2; ++mt) {
        int m0 = wm * 32 + mt * 16;
#pragma unroll
        for (int nt = 0; nt < 4; ++nt) {
            int nh = wn * 16 + nt * 4 + lb;       // half2 column index, 0..63
            H2[(m0 + la) * HPITCH2 + nh]     = cvt2(silu(acc[mt][nt][0]), silu(acc[mt][nt][1]));
            H2[(m0 + 8 + la) * HPITCH2 + nh] = cvt2(silu(acc[mt][nt][2]), silu(acc[mt][nt][3]));
        }
    }

    // ---- GEMM2 acc init: b2[n] ----
#pragma unroll
    for (int nt = 0; nt < 4; ++nt) {
        int n0 = wn * 32 + nt * 8 + 2 * lb;
        float bb0 = sC[128 + n0], bb1 = sC[128 + n0 + 1];
#pragma unroll
        for (int mt = 0; mt < 2; ++mt) {
            acc[mt][nt][0] = bb0; acc[mt][nt][1] = bb1;
            acc[mt][nt][2] = bb0; acc[mt][nt][3] = bb1;
        }
    }

    CPWAIT(0);
    __syncthreads();                              // H + all W2 visible to all warps

    // ---- GEMM2: H1 @ W2, K=128, NO intermediate barriers ----
#pragma unroll
    for (int c = 0; c < 4; ++c) {
        const uint32_t* Wt = reinterpret_cast<const uint32_t*>(smem + WB(c));
#pragma unroll
        for (int kt = 0; kt < 2; ++kt) {
            int kh = c * 16 + kt * 8;             // half2 k-offset in H
            uint32_t a[2][4];
#pragma unroll
            for (int mt = 0; mt < 2; ++mt) {
                int m0 = wm * 32 + mt * 16;
                a[mt][0] = H2[(m0 + la) * HPITCH2 + kh + lb];
                a[mt][1] = H2[(m0 + 8 + la) * HPITCH2 + kh + lb];
                a[mt][2] = H2[(m0 + la) * HPITCH2 + kh + 4 + lb];
                a[mt][3] = H2[(m0 + 8 + la) * HPITCH2 + kh + 4 + lb];
            }
#pragma unroll
            for (int nt = 0; nt < 4; ++nt) {
                int n0 = wn * 32 + nt * 8;
                uint32_t b0 = Wt[(n0 + la) * BPITCH2 + kt * 8 + lb];
                uint32_t b1 = Wt[(n0 + la) * BPITCH2 + kt * 8 + 4 + lb];
                mma16(acc[0][nt], a[0], b0, b1);
                mma16(acc[1][nt], a[1], b0, b1);
            }
        }
    }
    __syncthreads();

    // ---- epilogue2: silu(D2) . W3 -> partials -> sRed [64][16] ----
#pragma unroll
    for (int mt = 0; mt < 2; ++mt) {
#pragma unroll
        for (int half = 0; half < 2; ++half) {
            float p = 0.0f;
#pragma unroll
            for (int nt = 0; nt < 4; ++nt) {
                int n0 = wn * 32 + nt * 8 + 2 * lb;
                float v0 = acc[mt][nt][half * 2 + 0];
                float v1 = acc[mt][nt][half * 2 + 1];
                p = fmaf(silu(v0), sC[256 + n0], p);
                p = fmaf(silu(v1), sC[256 + n0 + 1], p);
            }
            int m = wm * 32 + mt * 16 + half * 8 + la;   // 0..63
            sRed[m * 16 + wn * 4 + lb] = p;
        }
    }
    __syncthreads();

    if (tid < GSIZE) {
        float s = 0.0f;
#pragma unroll
        for (int t = 0; t < 16; ++t) s += sRed[tid * 16 + t];
        sLog[tid] = (s + b3v) * ikT;
    }
    __syncthreads();

    // ---- per-graph softmax: warp 0, each lane owns 2 logits ----
    if (tid < 32) {
        float a  = sLog[tid];
        float b  = sLog[tid + 32];
        float mx = fmaxf(a, b);
#pragma unroll
        for (int o = 16; o; o >>= 1) mx = fmaxf(mx, __shfl_xor_sync(0xffffffffu, mx, o));
        float e0 = expf(a - mx), e1 = expf(b - mx);
        float s = e0 + e1;
#pragma unroll
        for (int o = 16; o; o >>= 1) s += __shfl_xor_sync(0xffffffffu, s, o);
        float inv = 1.0f / s;
        out[row0 + tid]      = e0 * inv;
        out[row0 + tid + 32] = e1 * inv;
    }
}

// ---------------- launcher ----------------
extern "C" void kernel_launch(void* const* d_in, const int* in_sizes, int n_in,
                              void* d_out, int out_size) {
    const float* X  = (const float*)d_in[0];
    const float* W1 = (const float*)d_in[1];
    const float* b1 = (const float*)d_in[2];
    const float* W2 = (const float*)d_in[3];
    const float* b2 = (const float*)d_in[4];
    const float* W3 = (const float*)d_in[5];
    const float* b3 = (const float*)d_in[6];
    const float* kT = (const float*)d_in[7];
    const int*   ei = (const int*)d_in[8];
    float* out = (float*)d_out;

    conv_kernel<<<64, 256>>>(W1, W2);             // zero deg + fp16 weights (coalesced)
    deg_kernel<<<EDGES / 4 / 256, 256>>>(ei);

    cudaFuncSetAttribute(mlp_kernel, cudaFuncAttributeMaxDynamicSharedMemorySize,
                         SMEM_BYTES);
    mlp_kernel<<<NGRAPH, 256, SMEM_BYTES>>>(X, W1, b1, b2, W3, b3, kT, out);
}